// round 12
// baseline (speedup 1.0000x reference)
#include <cuda_runtime.h>
#include <cuda_fp16.h>
#include <cstdint>

#define BATCH 2048
#define MF    26
#define KE    32
#define C1    (MF*MF)
#define NPAIR 351
#define NTRI  3276
#define NJ    3328
#define OUTW  256
#define FSTR  3712
#define FEATB 1024
#define NKS   13            // gemm1 k-splits (256 k each)

typedef unsigned long long ull;

__device__ int    g_e2pqj[NTRI];
__device__ int    g_meta2[384];
__device__ float  g_W1s[384 * 128];       // [pq][i]; row 351 = b1
__device__ float  g_W2t[NJ * 128];        // [i][j*128+h], i-row stride NJ
__device__ float  g_U[352 * NJ];          // [pq][j*128+h]; row 351 = v
__device__ float  g_F[BATCH * FSTR];      // cols 0..351 used (out1 GEMM)
__device__ __half g_Th[BATCH * NJ];       // T hi  [b][e]
__device__ __half g_Tl[BATCH * NJ];       // T lo
__device__ __half g_Uh[128 * NJ];         // Up^T hi [h][e]
__device__ __half g_Ul[128 * NJ];         // Up^T lo
__device__ float  g_P[NKS * BATCH * 128];

#define FMA2(a, x, y) asm("fma.rn.f32x2 %0, %1, %2, %0;" : "+l"(a) : "l"(x), "l"(y))
#define MUL2(d, x, y) asm("mul.rn.f32x2 %0, %1, %2;" : "=l"(d) : "l"(x), "l"(y))
#define ADD2(a, x)    asm("add.rn.f32x2 %0, %0, %1;" : "+l"(a) : "l"(x))
#define DUP2(d, f)    asm("mov.b64 %0, {%1, %1};" : "=l"(d) : "f"(f))

__device__ __forceinline__ unsigned sptr(const void* p) {
    return (unsigned)__cvta_generic_to_shared(p);
}
__device__ __forceinline__ void cp16(unsigned s, const void* g) {
    asm volatile("cp.async.cg.shared.global [%0], [%1], 16;\n" :: "r"(s), "l"(g));
}
#define CP_COMMIT() asm volatile("cp.async.commit_group;\n" ::)
#define CP_WAIT0()  asm volatile("cp.async.wait_group 0;\n" ::)
#define CP_WAIT1()  asm volatile("cp.async.wait_group 1;\n" ::)

#define LDSM4(r0, r1, r2, r3, addr) \
    asm volatile("ldmatrix.sync.aligned.m8n8.x4.shared.b16 {%0,%1,%2,%3}, [%4];" \
        : "=r"(r0), "=r"(r1), "=r"(r2), "=r"(r3) : "r"(addr))
#define LDSM2(r0, r1, addr) \
    asm volatile("ldmatrix.sync.aligned.m8n8.x2.shared.b16 {%0,%1}, [%2];" \
        : "=r"(r0), "=r"(r1) : "r"(addr))
#define MMA16816(d, a, b) \
    asm volatile("mma.sync.aligned.m16n8k16.row.col.f32.f16.f16.f32 " \
        "{%0,%1,%2,%3}, {%4,%5,%6,%7}, {%8,%9}, {%0,%1,%2,%3};" \
        : "+f"((d)[0]), "+f"((d)[1]), "+f"((d)[2]), "+f"((d)[3]) \
        : "r"((a)[0]), "r"((a)[1]), "r"((a)[2]), "r"((a)[3]), "r"((b)[0]), "r"((b)[1]))

__device__ __forceinline__ int pq_off(int p) { return p * MF - (p * (p - 1)) / 2; }

__device__ __forceinline__ void pq_decode(int pq, int& p, int& q) {
    p = (int)(26.5f - sqrtf(702.25f - 2.0f * (float)pq));
    if (p < 0) p = 0;
    while (p > 0 && pq_off(p) > pq) p--;
    while (pq_off(p + 1) <= pq) p++;
    q = p + (pq - pq_off(p));
}

__device__ __forceinline__ float hadd2(ull a) {
    float2 f = *reinterpret_cast<float2*>(&a);
    return f.x + f.y;
}

// ---------------------------------------------------------------------------
// kA_prep: [0,416) W2 transpose; [416,608) W1s; [608,621) e2pqj; [621] meta2
// ---------------------------------------------------------------------------
__global__ __launch_bounds__(256) void kA_prep(
    const float* __restrict__ W1, const float* __restrict__ b1,
    const float* __restrict__ W2)
{
    const int bx = blockIdx.x;
    const int t  = threadIdx.x;
    if (bx < 416) {
        __shared__ float tile[32][33];
        int c0 = (bx % 104) * 32;
        int h0 = (bx / 104) * 32;
        int tx = t & 31, ty = t >> 5;
#pragma unroll
        for (int r = 0; r < 4; r++)
            tile[ty + 8 * r][tx] = W2[(size_t)(h0 + ty + 8 * r) * NJ + c0 + tx];
        __syncthreads();
#pragma unroll
        for (int r = 0; r < 4; r++)
            g_W2t[(size_t)(c0 + ty + 8 * r) * 128 + h0 + tx] = tile[tx][ty + 8 * r];
    } else if (bx < 608) {
        int idx = (bx - 416) * 256 + t;           // 384*128
        int pq = idx >> 7, i = idx & 127;
        float v = 0.f;
        if (pq == NPAIR) v = b1[i];
        else if (pq < NPAIR) {
            int p, q; pq_decode(pq, p, q);
            v = W1[i * C1 + p * MF + q];
            if (p < q) v += W1[i * C1 + q * MF + p];
        }
        g_W1s[idx] = v;
    } else if (bx < 621) {
        int e = (bx - 608) * 256 + t;
        if (e < NTRI) {
            int rem = e, p = 0;
            while (rem >= (MF - p) * (MF - p + 1) / 2) { rem -= (MF - p) * (MF - p + 1) / 2; p++; }
            int q = p;
            while (rem >= MF - q) { rem -= MF - q; q++; }
            g_e2pqj[e] = p | (q << 8) | ((q + rem) << 16);
        }
    } else {
        for (int eq = t; eq < 384; eq += 256) {
            int v = 0;
            if (eq < NPAIR) {
                int q = 0;
                while ((q + 1) * (q + 2) / 2 <= eq) q++;
                int p = eq - q * (q + 1) / 2;
                int rb = 0;
                for (int pp = 0; pp < p; pp++) rb += (MF - pp) * (MF - pp + 1) / 2;
                rb += (MF - p) * (MF - p + 1) / 2 - (MF - q) * (MF - q + 1) / 2;
                v = p | (q << 5) | (rb << 10);
            }
            g_meta2[eq] = v;
        }
    }
}

// ---------------------------------------------------------------------------
// kB: [0,1024) feat; [1024,1232) k_u tiles 48m x 128n
// ---------------------------------------------------------------------------
__global__ __launch_bounds__(384) void kB(const float* __restrict__ x0g) {
    __shared__ __align__(16) char smem_pool[37248];
    const int t = threadIdx.x;

    if (blockIdx.x >= FEATB) {
        // ---- k_u ----
        float (*As)[52]  = reinterpret_cast<float(*)[52]>(smem_pool);
        float (*Bs)[132] = reinterpret_cast<float(*)[132]>(smem_pool + 6656);
        int ub = blockIdx.x - FEATB;
        int m0 = (ub & 7) * 48;
        int n0 = (ub >> 3) * 128;
        const int tx = t & 31, ty = t >> 5;

        ull acc[4][2];
#pragma unroll
        for (int r = 0; r < 4; r++) { acc[r][0] = 0ULL; acc[r][1] = 0ULL; }

        for (int kc = 0; kc < 128; kc += 32) {
            __syncthreads();
            {
                int row = t >> 3, c4 = t & 7;
                float4 v = *reinterpret_cast<const float4*>(
                    g_W1s + (size_t)(m0 + row) * 128 + kc + 4 * c4);
                As[4 * c4 + 0][row] = v.x;
                As[4 * c4 + 1][row] = v.y;
                As[4 * c4 + 2][row] = v.z;
                As[4 * c4 + 3][row] = v.w;
            }
#pragma unroll
            for (int l = 0; l < 3; l++) {
                int idx = t + 384 * l;
                if (idx < 1024) {
                    int row = idx >> 5, c4 = idx & 31;
                    *reinterpret_cast<float4*>(&Bs[row][4 * c4]) =
                        *reinterpret_cast<const float4*>(g_W2t + (size_t)(kc + row) * NJ + n0 + 4 * c4);
                }
            }
            __syncthreads();

#pragma unroll
            for (int kk = 0; kk < 32; kk++) {
                float4 a = *reinterpret_cast<const float4*>(&As[kk][4 * ty]);
                ulonglong2 w = *reinterpret_cast<const ulonglong2*>(&Bs[kk][4 * tx]);
                ull d;
                DUP2(d, a.x); FMA2(acc[0][0], w.x, d); FMA2(acc[0][1], w.y, d);
                DUP2(d, a.y); FMA2(acc[1][0], w.x, d); FMA2(acc[1][1], w.y, d);
                DUP2(d, a.z); FMA2(acc[2][0], w.x, d); FMA2(acc[2][1], w.y, d);
                DUP2(d, a.w); FMA2(acc[3][0], w.x, d); FMA2(acc[3][1], w.y, d);
            }
        }
#pragma unroll
        for (int r = 0; r < 4; r++) {
            int m = m0 + 4 * ty + r;
            if (m < 352) {
                float* dst = g_U + (size_t)m * NJ + n0 + 4 * tx;
                *reinterpret_cast<float2*>(dst)     = *reinterpret_cast<float2*>(&acc[r][0]);
                *reinterpret_cast<float2*>(dst + 2) = *reinterpret_cast<float2*>(&acc[r][1]);
            }
        }
        return;
    }

    // ---- feat ----
    ull   (*xsr)[MF][18] = reinterpret_cast<ull(*)[MF][18]>(smem_pool);
    float (*sF)[FSTR]    = reinterpret_cast<float(*)[FSTR]>(smem_pool + 7488);
    const int b0 = blockIdx.x * 2;

    for (int idx = t; idx < 832; idx += 384) {
        int s = idx >= 416; int r = idx - 416 * s;
        int j = r >> 4, kp = r & 15;
        xsr[s][j][kp] = *reinterpret_cast<const ull*>(
            x0g + (size_t)(b0 + s) * (MF * KE) + j * KE + 2 * kp);
    }
    if (t < 2) sF[t][351] = 32.0f;
    __syncthreads();

    if (t < 52) {   // sx
        int s = t >= 26; int j = t - 26 * s;
        ull s0 = 0, s1 = 0;
#pragma unroll
        for (int cc = 0; cc < 8; cc++) {
            ulonglong2 v = *reinterpret_cast<const ulonglong2*>(&xsr[s][j][2 * cc]);
            ADD2(s0, v.x); ADD2(s1, v.y);
        }
        ADD2(s0, s1);
        sF[s][3628 + j] = hadd2(s0);
    }

    const int w = t >> 5, lane = t & 31;
    const int s   = w & 1;
    const int seg = (int)((0x335522441100ULL >> (4 * w)) & 15);
    const int js  = (seg == 0) ? 0 : (seg == 1) ? 10 : (seg == 2) ? 15
                  : (seg == 3) ? 19 : (seg == 4) ? 22 : 24;

    const int eqA = seg * 64 + 2 * lane;
    const int eqB = eqA + 1;
    const bool vA = eqA < NPAIR, vB = eqB < NPAIR;
    const int mA = g_meta2[eqA], mB = g_meta2[eqB];
    const int pA = mA & 31, qA = (mA >> 5) & 31, rbA = mA >> 10;
    const int pB = mB & 31, qB = (mB >> 5) & 31, rbB = mB >> 10;

    ull xxA[16], xxB[16];
#pragma unroll
    for (int cc = 0; cc < 8; cc++) {
        ulonglong2 xp = *reinterpret_cast<const ulonglong2*>(&xsr[s][pA][2 * cc]);
        ulonglong2 xq = *reinterpret_cast<const ulonglong2*>(&xsr[s][qA][2 * cc]);
        MUL2(xxA[2 * cc],     xp.x, xq.x);
        MUL2(xxA[2 * cc + 1], xp.y, xq.y);
    }
#pragma unroll
    for (int cc = 0; cc < 8; cc++) {
        ulonglong2 xp = *reinterpret_cast<const ulonglong2*>(&xsr[s][pB][2 * cc]);
        ulonglong2 xq = *reinterpret_cast<const ulonglong2*>(&xsr[s][qB][2 * cc]);
        MUL2(xxB[2 * cc],     xp.x, xq.x);
        MUL2(xxB[2 * cc + 1], xp.y, xq.y);
    }

    {   // G
        ull g0 = 0, g1 = 0;
#pragma unroll
        for (int kp = 0; kp < 16; kp += 2) { ADD2(g0, xxA[kp]); ADD2(g1, xxA[kp + 1]); }
        ADD2(g0, g1);
        if (vA) sF[s][pq_off(pA) + qA - pA] = hadd2(g0);
        ull h0 = 0, h1 = 0;
#pragma unroll
        for (int kp = 0; kp < 16; kp += 2) { ADD2(h0, xxB[kp]); ADD2(h1, xxB[kp + 1]); }
        ADD2(h0, h1);
        if (vB) sF[s][pq_off(pB) + qB - pB] = hadd2(h0);
    }

    for (int j = js; j < MF; j++) {
        ull a0 = 0, a1 = 0, c0 = 0, c1 = 0;
#pragma unroll
        for (int cc = 0; cc < 8; cc++) {
            ulonglong2 xj = *reinterpret_cast<const ulonglong2*>(&xsr[s][j][2 * cc]);
            FMA2(a0, xxA[2 * cc],     xj.x);
            FMA2(a1, xxA[2 * cc + 1], xj.y);
            FMA2(c0, xxB[2 * cc],     xj.x);
            FMA2(c1, xxB[2 * cc + 1], xj.y);
        }
        ADD2(a0, a1); ADD2(c0, c1);
        if (vA && j >= qA) sF[s][352 + rbA + j - qA] = hadd2(a0);
        if (vB && j >= qB) sF[s][352 + rbB + j - qB] = hadd2(c0);
    }
    __syncthreads();

    // g_F cols 0..351 (fp32, out1 GEMM)
    for (int idx = t; idx < 176; idx += 384) {
        int s2 = idx >= 88; int r = idx - 88 * s2;
        *reinterpret_cast<float4*>(g_F + (size_t)(b0 + s2) * FSTR + 4 * r) =
            *reinterpret_cast<const float4*>(&sF[s2][4 * r]);
    }

    // T hi/lo fp16 [b][3328]
    for (int idx = t; idx < 2 * NJ; idx += 384) {
        int s2 = idx >= NJ; int e = idx - NJ * s2;
        float val;
        if (e < NTRI)            val = sF[s2][352 + e];
        else if (e < NTRI + MF)  val = sF[s2][3628 + (e - NTRI)];
        else if (e == NTRI + MF) val = 32.0f;
        else                     val = 0.0f;
        __half hi = __float2half_rn(val);
        float lo = val - __half2float(hi);
        size_t o = (size_t)(b0 + s2) * NJ + e;
        g_Th[o] = hi;
        g_Tl[o] = __float2half_rn(lo);
    }
}

// ---------------------------------------------------------------------------
// k_fold: block = 64e x 128h tile; coalesced g_U reads (h-fast), smem
//   transpose, coalesced g_Uh/g_Ul writes (e-fast). grid 52.
// ---------------------------------------------------------------------------
__global__ __launch_bounds__(256) void k_fold(const float* __restrict__ b2) {
    __shared__ float tile[64][129];
    const int t  = threadIdx.x;
    const int e0 = blockIdx.x * 64;
    const int h  = t & 127;
    const int eh = t >> 7;           // 0..1

#pragma unroll 4
    for (int i = 0; i < 32; i++) {
        int el = eh * 32 + i;
        int e = e0 + el;
        float val = 0.f;
        if (e < NTRI) {
            int c = g_e2pqj[e];
            int p = c & 255, q = (c >> 8) & 255, j = (c >> 16) & 255;
            #define CU(PQ, J) g_U[(size_t)(PQ) * NJ + (J) * 128 + h]
            if (p < q) {
                if (q < j) val = CU(pq_off(p) + q - p, j) + CU(pq_off(p) + j - p, q) + CU(pq_off(q) + j - q, p);
                else       val = CU(pq_off(p) + q - p, q) + CU(pq_off(q), p);
            } else {
                if (q < j) val = CU(pq_off(p), j) + CU(pq_off(p) + j - p, p);
                else       val = CU(pq_off(p), p);
            }
            #undef CU
        } else if (e < NTRI + MF) {
            val = g_U[(size_t)NPAIR * NJ + (e - NTRI) * 128 + h];
        } else if (e == NTRI + MF) {
            val = b2[h];
        }
        tile[el][h] = val;
    }
    __syncthreads();

    for (int idx = t; idx < 8192; idx += 256) {
        int h2 = idx >> 6;
        int el = idx & 63;
        float val = tile[el][h2];
        __half hi = __float2half_rn(val);
        float lo = val - __half2float(hi);
        size_t o = (size_t)h2 * NJ + e0 + el;
        g_Uh[o] = hi;
        g_Ul[o] = __float2half_rn(lo);
    }
}

// ---------------------------------------------------------------------------
// fp32 gemm core (out1): 64b x 128h, cp.async W, double buffer.
// ---------------------------------------------------------------------------
__device__ __forceinline__ void gemm_core(
    const float* __restrict__ Wrows,
    const float* __restrict__ Frow,
    int nchunks, int b0,
    float* __restrict__ dst, int dstr,
    float* As, float* Ws)
{
    const int t  = threadIdx.x;
    const int hq = t & 31;
    const int bg = t >> 5;

    const int arow = (t + 0)   >> 3;
    const int brow = (t + 256) >> 3;
    const int ac4  = t & 7;
    const float* aSrc0 = Frow + (size_t)(b0 + arow) * FSTR + 4 * ac4;
    const float* aSrc1 = Frow + (size_t)(b0 + brow) * FSTR + 4 * ac4;

    ull acc[4][4];
#pragma unroll
    for (int bp = 0; bp < 4; bp++)
#pragma unroll
        for (int e = 0; e < 4; e++) acc[bp][e] = 0ULL;

    float4 ra0, ra1;
    unsigned wDst[4];
    const float* wSrc[4];
#pragma unroll
    for (int l = 0; l < 4; l++) {
        int idx = t + 256 * l;
        int row = idx >> 5, c4 = idx & 31;
        wDst[l] = sptr(Ws + row * 128 + 4 * c4);
        wSrc[l] = Wrows + (size_t)row * 128 + 4 * c4;
    }

    ra0 = *reinterpret_cast<const float4*>(aSrc0);
    ra1 = *reinterpret_cast<const float4*>(aSrc1);
#pragma unroll
    for (int l = 0; l < 4; l++) cp16(wDst[l], wSrc[l]);
    CP_COMMIT();
    {
        float* d0 = As + (4 * ac4) * 68;
        d0[arow] = ra0.x; d0[68 + arow] = ra0.y; d0[136 + arow] = ra0.z; d0[204 + arow] = ra0.w;
        d0[brow] = ra1.x; d0[68 + brow] = ra1.y; d0[136 + brow] = ra1.z; d0[204 + brow] = ra1.w;
    }
    if (nchunks > 1) {
        ra0 = *reinterpret_cast<const float4*>(aSrc0 + 32);
        ra1 = *reinterpret_cast<const float4*>(aSrc1 + 32);
    }

    for (int ch = 0; ch < nchunks; ch++) {
        const int cur = ch & 1;
        CP_WAIT0();
        __syncthreads();

        if (ch + 1 < nchunks) {
            const int nxt = cur ^ 1;
            float* dA = As + nxt * 2176 + (4 * ac4) * 68;
            dA[arow] = ra0.x; dA[68 + arow] = ra0.y; dA[136 + arow] = ra0.z; dA[204 + arow] = ra0.w;
            dA[brow] = ra1.x; dA[68 + brow] = ra1.y; dA[136 + brow] = ra1.z; dA[204 + brow] = ra1.w;
#pragma unroll
            for (int l = 0; l < 4; l++)
                cp16(wDst[l] + nxt * 16384, wSrc[l] + (size_t)(ch + 1) * 32 * 128);
            CP_COMMIT();
            if (ch + 2 < nchunks) {
                ra0 = *reinterpret_cast<const float4*>(aSrc0 + (ch + 2) * 32);
                ra1 = *reinterpret_cast<const float4*>(aSrc1 + (ch + 2) * 32);
            }
        }

        const float* Ab = As + cur * 2176;
        const float* Wb = Ws + cur * 4096;
#pragma unroll
        for (int kk = 0; kk < 32; kk++) {
            ulonglong2 aA = *reinterpret_cast<const ulonglong2*>(Ab + kk * 68 + 8 * bg);
            ulonglong2 aB = *reinterpret_cast<const ulonglong2*>(Ab + kk * 68 + 8 * bg + 4);
            float4 wv = *reinterpret_cast<const float4*>(Wb + kk * 128 + 4 * hq);
            ull w0, w1, w2, w3;
            DUP2(w0, wv.x); DUP2(w1, wv.y); DUP2(w2, wv.z); DUP2(w3, wv.w);
            FMA2(acc[0][0], aA.x, w0); FMA2(acc[0][1], aA.x, w1);
            FMA2(acc[0][2], aA.x, w2); FMA2(acc[0][3], aA.x, w3);
            FMA2(acc[1][0], aA.y, w0); FMA2(acc[1][1], aA.y, w1);
            FMA2(acc[1][2], aA.y, w2); FMA2(acc[1][3], aA.y, w3);
            FMA2(acc[2][0], aB.x, w0); FMA2(acc[2][1], aB.x, w1);
            FMA2(acc[2][2], aB.x, w2); FMA2(acc[2][3], aB.x, w3);
            FMA2(acc[3][0], aB.y, w0); FMA2(acc[3][1], aB.y, w1);
            FMA2(acc[3][2], aB.y, w2); FMA2(acc[3][3], aB.y, w3);
        }
    }

#pragma unroll
    for (int bp = 0; bp < 4; bp++) {
        int b = b0 + 8 * bg + 2 * bp;
#pragma unroll
        for (int e = 0; e < 4; e++) {
            float2 v = *reinterpret_cast<float2*>(&acc[bp][e]);
            dst[(size_t)b * dstr + 4 * hq + e]       = v.x;
            dst[(size_t)(b + 1) * dstr + 4 * hq + e] = v.y;
        }
    }
}

// ---------------------------------------------------------------------------
// k_tc: grid 448, dyn smem 98304 (2 stages x 48K).
//   id<416: HMMA gemm1 tile (64b x 128h, K=256 = 4 chunks of 64),
//     double-buffered cp.async pipeline, fp16 split (3 MMA passes).
//   id>=416: fp32 gemm0 tile.
// Per-stage layout: A hi 0..8K, A lo 8..16K, B hi 16..32K, B lo 32..48K.
// ---------------------------------------------------------------------------
#define STAGE_BYTES 49152
__global__ __launch_bounds__(256) void k_tc(float* __restrict__ out) {
    extern __shared__ __align__(16) char dyn[];
    const int t = threadIdx.x;
    const int id = blockIdx.x;

    if (id >= 416) {
        float* As = reinterpret_cast<float*>(dyn);
        float* Ws = reinterpret_cast<float*>(dyn + 17408);
        gemm_core(g_W1s, g_F, 11, 64 * (id - 416), out, OUTW, As, Ws);
        return;
    }

    const int bt = id / NKS, ks = id - bt * NKS;
    const int b0 = bt * 64;
    const int kbase = ks * 256;
    const int wid = t >> 5, lane = t & 31;
    const int wm = wid >> 2, wn = wid & 3;
    const int mr0 = 32 * wm, nr0 = 32 * wn;

    const uint32_t sBase = sptr(dyn);

    float d[2][4][4];
#pragma unroll
    for (int mf = 0; mf < 2; mf++)
#pragma unroll
        for (int nf = 0; nf < 4; nf++)
#pragma unroll
            for (int e = 0; e < 4; e++) d[mf][nf][e] = 0.f;

    // stage-load coords (per thread, stage-invariant)
    const int aR = t >> 3, aC = t & 7;         // A: rows 0..31 per i-step of 32
    const uint32_t aSw0 = (uint32_t)(aR * 128 + ((aC ^ (aR & 7)) << 4));
    const int aR1 = (t + 256) >> 3;
    const uint32_t aSw1 = (uint32_t)(aR1 * 128 + ((aC ^ (aR1 & 7)) << 4));

    // ldmatrix lane-address components
    const int aRowOff = lane & 15;
    const uint32_t aColX = (uint32_t)((lane >> 4) << 4);
    const int bRowOff = lane & 7;
    const uint32_t bColX = (uint32_t)(((lane >> 3) & 1) << 4);

    // issue stage ch into buffer (ch&1)
    auto stage_issue = [&](int ch) {
        const int kc = kbase + ch * 64;
        const uint32_t sb = sBase + (uint32_t)(ch & 1) * STAGE_BYTES;
        {   // A hi/lo: 512 chunks each
            size_t go0 = (size_t)(b0 + aR) * NJ + kc + aC * 8;
            size_t go1 = (size_t)(b0 + aR1) * NJ + kc + aC * 8;
            cp16(sb + aSw0,        g_Th + go0);
            cp16(sb + 8192 + aSw0, g_Tl + go0);
            cp16(sb + aSw1,        g_Th + go1);
            cp16(sb + 8192 + aSw1, g_Tl + go1);
        }
#pragma unroll
        for (int i = 0; i < 4; i++) {   // B hi/lo: 1024 chunks each
            int u = t + 256 * i;
            int r = u >> 3, c8 = u & 7;
            uint32_t sw = (uint32_t)(r * 128 + ((c8 ^ (r & 7)) << 4));
            size_t go = (size_t)r * NJ + kc + c8 * 8;
            cp16(sb + 16384 + sw, g_Uh + go);
            cp16(sb + 32768 + sw, g_Ul + go);
        }
        CP_COMMIT();
    };

    stage_issue(0);
    stage_issue(1);

#pragma unroll
    for (int ch = 0; ch < 4; ch++) {
        if (ch < 3) { CP_WAIT1(); } else { CP_WAIT0(); }
        __syncthreads();

        const uint32_t sb = sBase + (uint32_t)(ch & 1) * STAGE_BYTES;
        const uint32_t sA = sb, sB = sb + 16384;

#pragma unroll
        for (int k16 = 0; k16 < 4; k16++) {
            uint32_t ah[2][4], al[2][4], bhf[4][2], blf[4][2];
#pragma unroll
            for (int mf = 0; mf < 2; mf++) {
                int row = mr0 + 16 * mf + aRowOff;
                uint32_t colb = (uint32_t)(k16 * 32) + aColX;
                uint32_t addr = sA + (uint32_t)(row * 128) + (colb ^ ((uint32_t)(row & 7) << 4));
                LDSM4(ah[mf][0], ah[mf][1], ah[mf][2], ah[mf][3], addr);
                LDSM4(al[mf][0], al[mf][1], al[mf][2], al[mf][3], addr + 8192);
            }
#pragma unroll
            for (int nf = 0; nf < 4; nf++) {
                int row = nr0 + 8 * nf + bRowOff;
                uint32_t colb = (uint32_t)(k16 * 32) + bColX;
                uint32_t addr = sB + (uint32_t)(row * 128) + (colb ^ ((uint32_t)(row & 7) << 4));
                LDSM2(bhf[nf][0], bhf[nf][1], addr);
                LDSM2(blf[nf][0], blf[nf][1], addr + 16384);
            }
#pragma unroll
            for (int mf = 0; mf < 2; mf++)
#pragma unroll
                for (int nf = 0; nf < 4; nf++) {
                    MMA16816(d[mf][nf], ah[mf], bhf[nf]);
                    MMA16816(d[mf][nf], ah[mf], blf[nf]);
                    MMA16816(d[mf][nf], al[mf], bhf[nf]);
                }
        }

        __syncthreads();
        if (ch + 2 < 4) stage_issue(ch + 2);
    }

    // epilogue
    float* P = g_P + (size_t)ks * BATCH * 128;
    const int g = lane >> 2, tq = lane & 3;
#pragma unroll
    for (int mf = 0; mf < 2; mf++) {
        int rbase = b0 + mr0 + 16 * mf;
#pragma unroll
        for (int nf = 0; nf < 4; nf++) {
            int h = nr0 + 8 * nf + 2 * tq;
            *reinterpret_cast<float2*>(P + (size_t)(rbase + g) * 128 + h) =
                make_float2(d[mf][nf][0], d[mf][nf][1]);
            *reinterpret_cast<float2*>(P + (size_t)(rbase + g + 8) * 128 + h) =
                make_float2(d[mf][nf][2], d[mf][nf][3]);
        }
    }
}

// ---------------------------------------------------------------------------
// k_red: out[:,128:256] = sum of 13 partials
// ---------------------------------------------------------------------------
__global__ void k_red(float* __restrict__ out) {
    int gid = blockIdx.x * blockDim.x + threadIdx.x;   // 2048*128
    int b = gid >> 7, h = gid & 127;
    const int N = BATCH * 128;
    float s0 = g_P[gid]          + g_P[gid + N];
    float s1 = g_P[gid + 2 * N]  + g_P[gid + 3 * N];
    float s2 = g_P[gid + 4 * N]  + g_P[gid + 5 * N];
    float s3 = g_P[gid + 6 * N]  + g_P[gid + 7 * N];
    float s4 = g_P[gid + 8 * N]  + g_P[gid + 9 * N];
    float s5 = g_P[gid + 10 * N] + g_P[gid + 11 * N];
    float s6 = g_P[gid + 12 * N];
    out[(size_t)b * OUTW + 128 + h] = ((s0 + s1) + (s2 + s3)) + ((s4 + s5) + s6);
}

// ---------------------------------------------------------------------------
extern "C" void kernel_launch(void* const* d_in, const int* in_sizes, int n_in,
                              void* d_out, int out_size) {
    const float* inputs = (const float*)d_in[0];
    const float* W1     = (const float*)d_in[1];
    const float* b1     = (const float*)d_in[2];
    const float* W2     = (const float*)d_in[3];
    const float* b2     = (const float*)d_in[4];
    float* out = (float*)d_out;

    cudaFuncSetAttribute(k_tc, cudaFuncAttributeMaxDynamicSharedMemorySize, 2 * STAGE_BYTES);

    kA_prep<<<622, 256>>>(W1, b1, W2);
    kB<<<FEATB + 208, 384>>>(inputs);
    k_fold<<<52, 256>>>(b2);
    k_tc<<<448, 256, 2 * STAGE_BYTES>>>(out);
    k_red<<<(BATCH * 128) / 256, 256>>>(out);
}

// round 13
// speedup vs baseline: 1.2112x; 1.2112x over previous
#include <cuda_runtime.h>
#include <cuda_fp16.h>
#include <cstdint>

#define BATCH 2048
#define MF    26
#define KE    32
#define C1    (MF*MF)
#define NPAIR 351
#define NTRI  3276
#define NJ    3328
#define OUTW  256
#define FSTR  3712
#define FEATB 1024
#define NKS   8             // gemm1 k-splits (7/7/7/7/6/6/6/6 chunks of 64)

typedef unsigned long long ull;

__device__ int    g_e2pqj[NTRI];
__device__ int    g_meta2[384];
__device__ float  g_W1s[384 * 128];       // [pq][i]; row 351 = b1, 352.. = 0
__device__ float  g_W2t[NJ * 128];        // [i][j*128+h], i-row stride NJ
__device__ float  g_U[352 * NJ];          // [pq][j*128+h]; row 351 = v
__device__ __half g_W1h[128 * 384];       // W1s^T hi [i][pq]
__device__ __half g_W1l[128 * 384];       // W1s^T lo
__device__ __half g_TFh[BATCH * 384];     // G-vector hi [b][e] (351=32, pad 0)
__device__ __half g_TFl[BATCH * 384];
__device__ __half g_Th[BATCH * NJ];       // T hi [b][e]
__device__ __half g_Tl[BATCH * NJ];
__device__ __half g_Uh[128 * NJ];         // Up^T hi [h][e]
__device__ __half g_Ul[128 * NJ];
__device__ float  g_P[NKS * BATCH * 128];

#define FMA2(a, x, y) asm("fma.rn.f32x2 %0, %1, %2, %0;" : "+l"(a) : "l"(x), "l"(y))
#define MUL2(d, x, y) asm("mul.rn.f32x2 %0, %1, %2;" : "=l"(d) : "l"(x), "l"(y))
#define ADD2(a, x)    asm("add.rn.f32x2 %0, %0, %1;" : "+l"(a) : "l"(x))
#define DUP2(d, f)    asm("mov.b64 %0, {%1, %1};" : "=l"(d) : "f"(f))

__device__ __forceinline__ unsigned sptr(const void* p) {
    return (unsigned)__cvta_generic_to_shared(p);
}
__device__ __forceinline__ void cp16(unsigned s, const void* g) {
    asm volatile("cp.async.cg.shared.global [%0], [%1], 16;\n" :: "r"(s), "l"(g));
}
#define CP_COMMIT() asm volatile("cp.async.commit_group;\n" ::)
#define CP_WAIT0()  asm volatile("cp.async.wait_group 0;\n" ::)
#define CP_WAIT1()  asm volatile("cp.async.wait_group 1;\n" ::)

#define LDSM4(r0, r1, r2, r3, addr) \
    asm volatile("ldmatrix.sync.aligned.m8n8.x4.shared.b16 {%0,%1,%2,%3}, [%4];" \
        : "=r"(r0), "=r"(r1), "=r"(r2), "=r"(r3) : "r"(addr))
#define LDSM2(r0, r1, addr) \
    asm volatile("ldmatrix.sync.aligned.m8n8.x2.shared.b16 {%0,%1}, [%2];" \
        : "=r"(r0), "=r"(r1) : "r"(addr))
#define MMA16816(d, a, b) \
    asm volatile("mma.sync.aligned.m16n8k16.row.col.f32.f16.f16.f32 " \
        "{%0,%1,%2,%3}, {%4,%5,%6,%7}, {%8,%9}, {%0,%1,%2,%3};" \
        : "+f"((d)[0]), "+f"((d)[1]), "+f"((d)[2]), "+f"((d)[3]) \
        : "r"((a)[0]), "r"((a)[1]), "r"((a)[2]), "r"((a)[3]), "r"((b)[0]), "r"((b)[1]))

__device__ __forceinline__ int pq_off(int p) { return p * MF - (p * (p - 1)) / 2; }

__device__ __forceinline__ void pq_decode(int pq, int& p, int& q) {
    p = (int)(26.5f - sqrtf(702.25f - 2.0f * (float)pq));
    if (p < 0) p = 0;
    while (p > 0 && pq_off(p) > pq) p--;
    while (pq_off(p + 1) <= pq) p++;
    q = p + (pq - pq_off(p));
}

__device__ __forceinline__ float hadd2(ull a) {
    float2 f = *reinterpret_cast<float2*>(&a);
    return f.x + f.y;
}

// ---------------------------------------------------------------------------
// kA_prep: [0,416) W2 transpose; [416,608) W1s (+fp16 transposed);
//          [608,621) e2pqj; [621] meta2
// ---------------------------------------------------------------------------
__global__ __launch_bounds__(256) void kA_prep(
    const float* __restrict__ W1, const float* __restrict__ b1,
    const float* __restrict__ W2)
{
    const int bx = blockIdx.x;
    const int t  = threadIdx.x;
    if (bx < 416) {
        __shared__ float tile[32][33];
        int c0 = (bx % 104) * 32;
        int h0 = (bx / 104) * 32;
        int tx = t & 31, ty = t >> 5;
#pragma unroll
        for (int r = 0; r < 4; r++)
            tile[ty + 8 * r][tx] = W2[(size_t)(h0 + ty + 8 * r) * NJ + c0 + tx];
        __syncthreads();
#pragma unroll
        for (int r = 0; r < 4; r++)
            g_W2t[(size_t)(c0 + ty + 8 * r) * 128 + h0 + tx] = tile[tx][ty + 8 * r];
    } else if (bx < 608) {
        int idx = (bx - 416) * 256 + t;           // 384*128
        int pq = idx >> 7, i = idx & 127;
        float v = 0.f;
        if (pq == NPAIR) v = b1[i];
        else if (pq < NPAIR) {
            int p, q; pq_decode(pq, p, q);
            v = W1[i * C1 + p * MF + q];
            if (p < q) v += W1[i * C1 + q * MF + p];
        }
        g_W1s[idx] = v;
        __half hi = __float2half_rn(v);
        g_W1h[(size_t)i * 384 + pq] = hi;
        g_W1l[(size_t)i * 384 + pq] = __float2half_rn(v - __half2float(hi));
    } else if (bx < 621) {
        int e = (bx - 608) * 256 + t;
        if (e < NTRI) {
            int rem = e, p = 0;
            while (rem >= (MF - p) * (MF - p + 1) / 2) { rem -= (MF - p) * (MF - p + 1) / 2; p++; }
            int q = p;
            while (rem >= MF - q) { rem -= MF - q; q++; }
            g_e2pqj[e] = p | (q << 8) | ((q + rem) << 16);
        }
    } else {
        for (int eq = t; eq < 384; eq += 256) {
            int v = 0;
            if (eq < NPAIR) {
                int q = 0;
                while ((q + 1) * (q + 2) / 2 <= eq) q++;
                int p = eq - q * (q + 1) / 2;
                int rb = 0;
                for (int pp = 0; pp < p; pp++) rb += (MF - pp) * (MF - pp + 1) / 2;
                rb += (MF - p) * (MF - p + 1) / 2 - (MF - q) * (MF - q + 1) / 2;
                v = p | (q << 5) | (rb << 10);
            }
            g_meta2[eq] = v;
        }
    }
}

// ---------------------------------------------------------------------------
// kB: [0,1024) feat; [1024,1232) k_u tiles 48m x 128n
// ---------------------------------------------------------------------------
__global__ __launch_bounds__(384) void kB(const float* __restrict__ x0g) {
    __shared__ __align__(16) char smem_pool[37248];
    const int t = threadIdx.x;

    if (blockIdx.x >= FEATB) {
        // ---- k_u ----
        float (*As)[52]  = reinterpret_cast<float(*)[52]>(smem_pool);
        float (*Bs)[132] = reinterpret_cast<float(*)[132]>(smem_pool + 6656);
        int ub = blockIdx.x - FEATB;
        int m0 = (ub & 7) * 48;
        int n0 = (ub >> 3) * 128;
        const int tx = t & 31, ty = t >> 5;

        ull acc[4][2];
#pragma unroll
        for (int r = 0; r < 4; r++) { acc[r][0] = 0ULL; acc[r][1] = 0ULL; }

        for (int kc = 0; kc < 128; kc += 32) {
            __syncthreads();
            {
                int row = t >> 3, c4 = t & 7;
                float4 v = *reinterpret_cast<const float4*>(
                    g_W1s + (size_t)(m0 + row) * 128 + kc + 4 * c4);
                As[4 * c4 + 0][row] = v.x;
                As[4 * c4 + 1][row] = v.y;
                As[4 * c4 + 2][row] = v.z;
                As[4 * c4 + 3][row] = v.w;
            }
#pragma unroll
            for (int l = 0; l < 3; l++) {
                int idx = t + 384 * l;
                if (idx < 1024) {
                    int row = idx >> 5, c4 = idx & 31;
                    *reinterpret_cast<float4*>(&Bs[row][4 * c4]) =
                        *reinterpret_cast<const float4*>(g_W2t + (size_t)(kc + row) * NJ + n0 + 4 * c4);
                }
            }
            __syncthreads();

#pragma unroll
            for (int kk = 0; kk < 32; kk++) {
                float4 a = *reinterpret_cast<const float4*>(&As[kk][4 * ty]);
                ulonglong2 w = *reinterpret_cast<const ulonglong2*>(&Bs[kk][4 * tx]);
                ull d;
                DUP2(d, a.x); FMA2(acc[0][0], w.x, d); FMA2(acc[0][1], w.y, d);
                DUP2(d, a.y); FMA2(acc[1][0], w.x, d); FMA2(acc[1][1], w.y, d);
                DUP2(d, a.z); FMA2(acc[2][0], w.x, d); FMA2(acc[2][1], w.y, d);
                DUP2(d, a.w); FMA2(acc[3][0], w.x, d); FMA2(acc[3][1], w.y, d);
            }
        }
#pragma unroll
        for (int r = 0; r < 4; r++) {
            int m = m0 + 4 * ty + r;
            if (m < 352) {
                float* dst = g_U + (size_t)m * NJ + n0 + 4 * tx;
                *reinterpret_cast<float2*>(dst)     = *reinterpret_cast<float2*>(&acc[r][0]);
                *reinterpret_cast<float2*>(dst + 2) = *reinterpret_cast<float2*>(&acc[r][1]);
            }
        }
        return;
    }

    // ---- feat ----
    ull   (*xsr)[MF][18] = reinterpret_cast<ull(*)[MF][18]>(smem_pool);
    float (*sF)[FSTR]    = reinterpret_cast<float(*)[FSTR]>(smem_pool + 7488);
    const int b0 = blockIdx.x * 2;

    for (int idx = t; idx < 832; idx += 384) {
        int s = idx >= 416; int r = idx - 416 * s;
        int j = r >> 4, kp = r & 15;
        xsr[s][j][kp] = *reinterpret_cast<const ull*>(
            x0g + (size_t)(b0 + s) * (MF * KE) + j * KE + 2 * kp);
    }
    __syncthreads();

    if (t < 52) {   // sx
        int s = t >= 26; int j = t - 26 * s;
        ull s0 = 0, s1 = 0;
#pragma unroll
        for (int cc = 0; cc < 8; cc++) {
            ulonglong2 v = *reinterpret_cast<const ulonglong2*>(&xsr[s][j][2 * cc]);
            ADD2(s0, v.x); ADD2(s1, v.y);
        }
        ADD2(s0, s1);
        sF[s][3628 + j] = hadd2(s0);
    }

    const int w = t >> 5, lane = t & 31;
    const int s   = w & 1;
    const int seg = (int)((0x335522441100ULL >> (4 * w)) & 15);
    const int js  = (seg == 0) ? 0 : (seg == 1) ? 10 : (seg == 2) ? 15
                  : (seg == 3) ? 19 : (seg == 4) ? 22 : 24;

    const int eqA = seg * 64 + 2 * lane;
    const int eqB = eqA + 1;
    const bool vA = eqA < NPAIR, vB = eqB < NPAIR;
    const int mA = g_meta2[eqA], mB = g_meta2[eqB];
    const int pA = mA & 31, qA = (mA >> 5) & 31, rbA = mA >> 10;
    const int pB = mB & 31, qB = (mB >> 5) & 31, rbB = mB >> 10;

    ull xxA[16], xxB[16];
#pragma unroll
    for (int cc = 0; cc < 8; cc++) {
        ulonglong2 xp = *reinterpret_cast<const ulonglong2*>(&xsr[s][pA][2 * cc]);
        ulonglong2 xq = *reinterpret_cast<const ulonglong2*>(&xsr[s][qA][2 * cc]);
        MUL2(xxA[2 * cc],     xp.x, xq.x);
        MUL2(xxA[2 * cc + 1], xp.y, xq.y);
    }
#pragma unroll
    for (int cc = 0; cc < 8; cc++) {
        ulonglong2 xp = *reinterpret_cast<const ulonglong2*>(&xsr[s][pB][2 * cc]);
        ulonglong2 xq = *reinterpret_cast<const ulonglong2*>(&xsr[s][qB][2 * cc]);
        MUL2(xxB[2 * cc],     xp.x, xq.x);
        MUL2(xxB[2 * cc + 1], xp.y, xq.y);
    }

    {   // G
        ull g0 = 0, g1 = 0;
#pragma unroll
        for (int kp = 0; kp < 16; kp += 2) { ADD2(g0, xxA[kp]); ADD2(g1, xxA[kp + 1]); }
        ADD2(g0, g1);
        if (vA) sF[s][pq_off(pA) + qA - pA] = hadd2(g0);
        ull h0 = 0, h1 = 0;
#pragma unroll
        for (int kp = 0; kp < 16; kp += 2) { ADD2(h0, xxB[kp]); ADD2(h1, xxB[kp + 1]); }
        ADD2(h0, h1);
        if (vB) sF[s][pq_off(pB) + qB - pB] = hadd2(h0);
    }

    for (int j = js; j < MF; j++) {
        ull a0 = 0, a1 = 0, c0 = 0, c1 = 0;
#pragma unroll
        for (int cc = 0; cc < 8; cc++) {
            ulonglong2 xj = *reinterpret_cast<const ulonglong2*>(&xsr[s][j][2 * cc]);
            FMA2(a0, xxA[2 * cc],     xj.x);
            FMA2(a1, xxA[2 * cc + 1], xj.y);
            FMA2(c0, xxB[2 * cc],     xj.x);
            FMA2(c1, xxB[2 * cc + 1], xj.y);
        }
        ADD2(a0, a1); ADD2(c0, c1);
        if (vA && j >= qA) sF[s][352 + rbA + j - qA] = hadd2(a0);
        if (vB && j >= qB) sF[s][352 + rbB + j - qB] = hadd2(c0);
    }
    __syncthreads();

    // G-vector fp16 hi/lo [b][384]: 0..350 G, 351=32, 352..383=0
    for (int idx = t; idx < 768; idx += 384) {
        int s2 = idx >= 384; int e = idx - 384 * s2;
        float val = (e < NPAIR) ? sF[s2][e] : (e == NPAIR ? 32.0f : 0.0f);
        __half hi = __float2half_rn(val);
        float lo = val - __half2float(hi);
        size_t o = (size_t)(b0 + s2) * 384 + e;
        g_TFh[o] = hi;
        g_TFl[o] = __float2half_rn(lo);
    }

    // T-vector fp16 hi/lo [b][3328]: 0..3275 T, 3276..3301 sx, 3302=32, rest 0
    for (int idx = t; idx < 2 * NJ; idx += 384) {
        int s2 = idx >= NJ; int e = idx - NJ * s2;
        float val;
        if (e < NTRI)            val = sF[s2][352 + e];
        else if (e < NTRI + MF)  val = sF[s2][3628 + (e - NTRI)];
        else if (e == NTRI + MF) val = 32.0f;
        else                     val = 0.0f;
        __half hi = __float2half_rn(val);
        float lo = val - __half2float(hi);
        size_t o = (size_t)(b0 + s2) * NJ + e;
        g_Th[o] = hi;
        g_Tl[o] = __float2half_rn(lo);
    }
}

// ---------------------------------------------------------------------------
// k_fold: grid (52, 4) — 64e x 32h tiles. Warp-uniform e reads (h-coalesced),
//   smem transpose, e-coalesced fp16 writes.
// ---------------------------------------------------------------------------
__global__ __launch_bounds__(256) void k_fold(const float* __restrict__ b2) {
    __shared__ float tile[64][33];
    const int t  = threadIdx.x;
    const int e0 = blockIdx.x * 64;
    const int h0 = blockIdx.y * 32;
    const int hl = t & 31;
    const int h  = h0 + hl;
    const int er = t >> 5;   // warp id 0..7

#pragma unroll
    for (int i = 0; i < 8; i++) {
        int el = er + 8 * i;        // uniform within warp
        int e = e0 + el;
        float val = 0.f;
        if (e < NTRI) {
            int c = g_e2pqj[e];
            int p = c & 255, q = (c >> 8) & 255, j = (c >> 16) & 255;
            #define CU(PQ, J) g_U[(size_t)(PQ) * NJ + (J) * 128 + h]
            if (p < q) {
                if (q < j) val = CU(pq_off(p) + q - p, j) + CU(pq_off(p) + j - p, q) + CU(pq_off(q) + j - q, p);
                else       val = CU(pq_off(p) + q - p, q) + CU(pq_off(q), p);
            } else {
                if (q < j) val = CU(pq_off(p), j) + CU(pq_off(p) + j - p, p);
                else       val = CU(pq_off(p), p);
            }
            #undef CU
        } else if (e < NTRI + MF) {
            val = g_U[(size_t)NPAIR * NJ + (e - NTRI) * 128 + h];
        } else if (e == NTRI + MF) {
            val = b2[h];
        }
        tile[el][hl] = val;
    }
    __syncthreads();

#pragma unroll
    for (int i = 0; i < 8; i++) {
        int idx = t + 256 * i;      // 0..2047
        int h2 = idx >> 6;          // 0..31
        int el = idx & 63;
        float val = tile[el][h2];
        __half hi = __float2half_rn(val);
        float lo = val - __half2float(hi);
        size_t o = (size_t)(h0 + h2) * NJ + e0 + el;
        g_Uh[o] = hi;
        g_Ul[o] = __float2half_rn(lo);
    }
}

// ---------------------------------------------------------------------------
// k_tc: grid 288 (single wave at 2 CTAs/SM), all HMMA, dyn smem 96K.
//   id<256: gemm1 tile (bt=id>>3, ks=id&7; chunks 7/7/7/7/6/6/6/6) -> g_P[ks]
//   id>=256: gemm0 tile (K=384, 6 chunks) -> out cols 0..127 direct
// Per-stage (48K): A hi 0..8K, A lo 8..16K, B hi 16..32K, B lo 32..48K.
// ---------------------------------------------------------------------------
#define STAGE_BYTES 49152
__global__ __launch_bounds__(256) void k_tc(float* __restrict__ out) {
    extern __shared__ __align__(16) char dyn[];
    const int t = threadIdx.x;
    const int id = blockIdx.x;
    const int wid = t >> 5, lane = t & 31;
    const int wm = wid >> 2, wn = wid & 3;
    const int mr0 = 32 * wm, nr0 = 32 * wn;

    const __half *Ah, *Al, *Bh, *Bl;
    int astr, bstr, nch, kbase, b0;
    float* dst;
    int dstr;
    if (id < 256) {
        int bt = id >> 3, ks = id & 7;
        b0 = bt * 64;
        Ah = g_Th; Al = g_Tl; Bh = g_Uh; Bl = g_Ul;
        astr = NJ; bstr = NJ;
        nch = (ks < 4) ? 7 : 6;
        kbase = 64 * ((ks < 4) ? 7 * ks : 28 + 6 * (ks - 4));
        dst = g_P + (size_t)ks * BATCH * 128;
        dstr = 128;
    } else {
        b0 = (id - 256) * 64;
        Ah = g_TFh; Al = g_TFl; Bh = g_W1h; Bl = g_W1l;
        astr = 384; bstr = 384;
        nch = 6; kbase = 0;
        dst = out;
        dstr = OUTW;
    }

    const uint32_t sBase = sptr(dyn);

    float d[2][4][4];
#pragma unroll
    for (int mf = 0; mf < 2; mf++)
#pragma unroll
        for (int nf = 0; nf < 4; nf++)
#pragma unroll
            for (int e = 0; e < 4; e++) d[mf][nf][e] = 0.f;

    const int aR = t >> 3, aC = t & 7;
    const uint32_t aSw0 = (uint32_t)(aR * 128 + ((aC ^ (aR & 7)) << 4));
    const int aR1 = (t + 256) >> 3;
    const uint32_t aSw1 = (uint32_t)(aR1 * 128 + ((aC ^ (aR1 & 7)) << 4));

    const int aRowOff = lane & 15;
    const uint32_t aColX = (uint32_t)((lane >> 4) << 4);
    const int bRowOff = lane & 7;
    const uint32_t bColX = (uint32_t)(((lane >> 3) & 1) << 4);

    auto stage_issue = [&](int ch) {
        const int kc = kbase + ch * 64;
        const uint32_t sb = sBase + (uint32_t)(ch & 1) * STAGE_BYTES;
        {
            size_t go0 = (size_t)(b0 + aR) * astr + kc + aC * 8;
            size_t go1 = (size_t)(b0 + aR1) * astr + kc + aC * 8;
            cp16(sb + aSw0,        Ah + go0);
            cp16(sb + 8192 + aSw0, Al + go0);
            cp16(sb + aSw1,        Ah + go1);
            cp16(sb + 8192 + aSw1, Al + go1);
        }
#pragma unroll
        for (int i = 0; i < 4; i++) {
            int u = t + 256 * i;
            int r = u >> 3, c8 = u & 7;
            uint32_t sw = (uint32_t)(r * 128 + ((c8 ^ (r & 7)) << 4));
            size_t go = (size_t)r * bstr + kc + c8 * 8;
            cp16(sb + 16384 + sw, Bh + go);
            cp16(sb + 32768 + sw, Bl + go);
        }
        CP_COMMIT();
    };

    stage_issue(0);
    if (nch > 1) stage_issue(1);

    for (int ch = 0; ch < nch; ch++) {
        if (ch + 1 < nch) { CP_WAIT1(); } else { CP_WAIT0(); }
        __syncthreads();

        const uint32_t sb = sBase + (uint32_t)(ch & 1) * STAGE_BYTES;
        const uint32_t sA = sb, sB = sb + 16384;

#pragma unroll
        for (int k16 = 0; k16 < 4; k16++) {
            uint32_t ah[2][4], al[2][4], bhf[4][2], blf[4][2];
#pragma unroll
            for (int mf = 0; mf < 2; mf++) {
                int row = mr0 + 16 * mf + aRowOff;
                uint32_t colb = (uint32_t)(k16 * 32) + aColX;
                uint32_t addr = sA + (uint32_t)(row * 128) + (colb ^ ((uint32_t)(row & 7) << 4));
                LDSM4(ah[mf][0], ah[mf][1], ah[mf][2], ah[mf][3], addr);
                LDSM4(al[mf][0], al[mf][1], al[mf][2], al[mf][3], addr + 8192);
            }
#pragma unroll
            for (int nf = 0; nf < 4; nf++) {
                int row = nr0 + 8 * nf + bRowOff;
                uint32_t colb = (uint32_t)(k16 * 32) + bColX;
                uint32_t addr = sB + (uint32_t)(row * 128) + (colb ^ ((uint32_t)(row & 7) << 4));
                LDSM2(bhf[nf][0], bhf[nf][1], addr);
                LDSM2(blf[nf][0], blf[nf][1], addr + 16384);
            }
#pragma unroll
            for (int mf = 0; mf < 2; mf++)
#pragma unroll
                for (int nf = 0; nf < 4; nf++) {
                    MMA16816(d[mf][nf], ah[mf], bhf[nf]);
                    MMA16816(d[mf][nf], ah[mf], blf[nf]);
                    MMA16816(d[mf][nf], al[mf], bhf[nf]);
                }
        }

        __syncthreads();
        if (ch + 2 < nch) stage_issue(ch + 2);
    }

    // epilogue
    const int g = lane >> 2, tq = lane & 3;
#pragma unroll
    for (int mf = 0; mf < 2; mf++) {
        int rbase = b0 + mr0 + 16 * mf;
#pragma unroll
        for (int nf = 0; nf < 4; nf++) {
            int h = nr0 + 8 * nf + 2 * tq;
            *reinterpret_cast<float2*>(dst + (size_t)(rbase + g) * dstr + h) =
                make_float2(d[mf][nf][0], d[mf][nf][1]);
            *reinterpret_cast<float2*>(dst + (size_t)(rbase + g + 8) * dstr + h) =
                make_float2(d[mf][nf][2], d[mf][nf][3]);
        }
    }
}

// ---------------------------------------------------------------------------
// k_red: out[:,128:256] = sum of 8 partials
// ---------------------------------------------------------------------------
__global__ void k_red(float* __restrict__ out) {
    int gid = blockIdx.x * blockDim.x + threadIdx.x;   // 2048*128
    int b = gid >> 7, h = gid & 127;
    const int N = BATCH * 128;
    float s0 = g_P[gid]         + g_P[gid + N];
    float s1 = g_P[gid + 2 * N] + g_P[gid + 3 * N];
    float s2 = g_P[gid + 4 * N] + g_P[gid + 5 * N];
    float s3 = g_P[gid + 6 * N] + g_P[gid + 7 * N];
    out[(size_t)b * OUTW + 128 + h] = (s0 + s1) + (s2 + s3);
}

// ---------------------------------------------------------------------------
extern "C" void kernel_launch(void* const* d_in, const int* in_sizes, int n_in,
                              void* d_out, int out_size) {
    const float* inputs = (const float*)d_in[0];
    const float* W1     = (const float*)d_in[1];
    const float* b1     = (const float*)d_in[2];
    const float* W2     = (const float*)d_in[3];
    const float* b2     = (const float*)d_in[4];
    float* out = (float*)d_out;

    cudaFuncSetAttribute(k_tc, cudaFuncAttributeMaxDynamicSharedMemorySize, 2 * STAGE_BYTES);

    kA_prep<<<622, 256>>>(W1, b1, W2);
    kB<<<FEATB + 208, 384>>>(inputs);
    k_fold<<<dim3(52, 4), 256>>>(b2);
    k_tc<<<288, 256, 2 * STAGE_BYTES>>>(out);
    k_red<<<(BATCH * 128) / 256, 256>>>(out);
}

// round 14
// speedup vs baseline: 1.3167x; 1.0872x over previous
#include <cuda_runtime.h>
#include <cuda_fp16.h>
#include <cstdint>

#define BATCH 2048
#define MF    26
#define KE    32
#define C1    (MF*MF)
#define NPAIR 351
#define NTRI  3276
#define NJ    3328
#define OUTW  256
#define NKS   8             // gemm1 k-splits (7/7/7/7/6/6/6/6 chunks of 64)

typedef unsigned long long ull;

__device__ int    g_e2pqj[NTRI];
__device__ float  g_W1s[384 * 128];       // [pq][i]; row 351 = b1, 352.. = 0
__device__ float  g_W2t[NJ * 128];        // [i][j*128+h], i-row stride NJ
__device__ float  g_U[352 * NJ];          // [pq][j*128+h]; row 351 = v
__device__ __half g_W1h[128 * 384];       // W1s^T hi [i][pq]
__device__ __half g_W1l[128 * 384];
__device__ __half g_TFh[BATCH * 384];     // G-vector hi [b][e] (351=32, pad 0)
__device__ __half g_TFl[BATCH * 384];
__device__ __half g_Th[BATCH * NJ];       // T hi [b][e]
__device__ __half g_Tl[BATCH * NJ];
__device__ __half g_Uh[128 * NJ];         // Up^T hi [h][e]
__device__ __half g_Ul[128 * NJ];
__device__ float  g_P[NKS * BATCH * 128];

#define FMA2(a, x, y) asm("fma.rn.f32x2 %0, %1, %2, %0;" : "+l"(a) : "l"(x), "l"(y))
#define MUL2(d, x, y) asm("mul.rn.f32x2 %0, %1, %2;" : "=l"(d) : "l"(x), "l"(y))
#define ADD2(a, x)    asm("add.rn.f32x2 %0, %0, %1;" : "+l"(a) : "l"(x))
#define DUP2(d, f)    asm("mov.b64 %0, {%1, %1};" : "=l"(d) : "f"(f))

__device__ __forceinline__ unsigned sptr(const void* p) {
    return (unsigned)__cvta_generic_to_shared(p);
}
__device__ __forceinline__ void cp16(unsigned s, const void* g) {
    asm volatile("cp.async.cg.shared.global [%0], [%1], 16;\n" :: "r"(s), "l"(g));
}
#define CP_COMMIT() asm volatile("cp.async.commit_group;\n" ::)
#define CP_WAIT0()  asm volatile("cp.async.wait_group 0;\n" ::)
#define CP_WAIT1()  asm volatile("cp.async.wait_group 1;\n" ::)

#define LDSM4(r0, r1, r2, r3, addr) \
    asm volatile("ldmatrix.sync.aligned.m8n8.x4.shared.b16 {%0,%1,%2,%3}, [%4];" \
        : "=r"(r0), "=r"(r1), "=r"(r2), "=r"(r3) : "r"(addr))
#define MMA16816(d, a, b) \
    asm volatile("mma.sync.aligned.m16n8k16.row.col.f32.f16.f16.f32 " \
        "{%0,%1,%2,%3}, {%4,%5,%6,%7}, {%8,%9}, {%0,%1,%2,%3};" \
        : "+f"((d)[0]), "+f"((d)[1]), "+f"((d)[2]), "+f"((d)[3]) \
        : "r"((a)[0]), "r"((a)[1]), "r"((a)[2]), "r"((a)[3]), "r"((b)[0]), "r"((b)[1]))

__device__ __forceinline__ int pq_off(int p) { return p * MF - (p * (p - 1)) / 2; }

__device__ __forceinline__ void pq_decode(int pq, int& p, int& q) {
    p = (int)(26.5f - sqrtf(702.25f - 2.0f * (float)pq));
    if (p < 0) p = 0;
    while (p > 0 && pq_off(p) > pq) p--;
    while (pq_off(p + 1) <= pq) p++;
    q = p + (pq - pq_off(p));
}

__device__ __forceinline__ float hadd2(ull a) {
    float2 f = *reinterpret_cast<float2*>(&a);
    return f.x + f.y;
}

// ---------------------------------------------------------------------------
// kA_prep: [0,416) W2 transpose; [416,608) W1s (+fp16 transposed); [608,621) e2pqj
// ---------------------------------------------------------------------------
__global__ __launch_bounds__(256) void kA_prep(
    const float* __restrict__ W1, const float* __restrict__ b1,
    const float* __restrict__ W2)
{
    const int bx = blockIdx.x;
    const int t  = threadIdx.x;
    if (bx < 416) {
        __shared__ float tile[32][33];
        int c0 = (bx % 104) * 32;
        int h0 = (bx / 104) * 32;
        int tx = t & 31, ty = t >> 5;
#pragma unroll
        for (int r = 0; r < 4; r++)
            tile[ty + 8 * r][tx] = W2[(size_t)(h0 + ty + 8 * r) * NJ + c0 + tx];
        __syncthreads();
#pragma unroll
        for (int r = 0; r < 4; r++)
            g_W2t[(size_t)(c0 + ty + 8 * r) * 128 + h0 + tx] = tile[tx][ty + 8 * r];
    } else if (bx < 608) {
        int idx = (bx - 416) * 256 + t;           // 384*128
        int pq = idx >> 7, i = idx & 127;
        float v = 0.f;
        if (pq == NPAIR) v = b1[i];
        else if (pq < NPAIR) {
            int p, q; pq_decode(pq, p, q);
            v = W1[i * C1 + p * MF + q];
            if (p < q) v += W1[i * C1 + q * MF + p];
        }
        g_W1s[idx] = v;
        __half hi = __float2half_rn(v);
        g_W1h[(size_t)i * 384 + pq] = hi;
        g_W1l[(size_t)i * 384 + pq] = __float2half_rn(v - __half2float(hi));
    } else {
        int e = (bx - 608) * 256 + t;
        if (e < NTRI) {
            int rem = e, p = 0;
            while (rem >= (MF - p) * (MF - p + 1) / 2) { rem -= (MF - p) * (MF - p + 1) / 2; p++; }
            int q = p;
            while (rem >= MF - q) { rem -= MF - q; q++; }
            g_e2pqj[e] = p | (q << 8) | ((q + rem) << 16);
        }
    }
}

// ---------------------------------------------------------------------------
// k_feat: 1 batch/block, 384 thr, 2 CTAs/SM. 11 q-major segments of 32
//   entries, 1 entry/lane, SMSP-balanced seg map, warp 8 idle in T phase.
// ---------------------------------------------------------------------------
__global__ __launch_bounds__(384, 2) void k_feat(const float* __restrict__ x0g) {
    __shared__ ull   xsr[MF][18];
    __shared__ float sF[3712];   // G 0..350 | T 352..3627 | sx 3628..3653
    const int b = blockIdx.x;
    const int t = threadIdx.x;

    for (int idx = t; idx < MF * 16; idx += 384) {
        int j = idx >> 4, kp = idx & 15;
        xsr[j][kp] = *reinterpret_cast<const ull*>(
            x0g + (size_t)b * (MF * KE) + j * KE + 2 * kp);
    }
    __syncthreads();

    if (t < MF) {   // sx
        ull s0 = 0, s1 = 0;
#pragma unroll
        for (int cc = 0; cc < 8; cc++) {
            ulonglong2 v = *reinterpret_cast<const ulonglong2*>(&xsr[t][2 * cc]);
            ADD2(s0, v.x); ADD2(s1, v.y);
        }
        ADD2(s0, s1);
        sF[3628 + t] = hadd2(s0);
    }

    const int w = t >> 5, lane = t & 31;
    // seg map (0xF = idle): w0..w11 -> 0,1,2,3,9,5,4,6,IDLE,10,8,7
    const int seg = (int)((0x78AF64593210ULL >> (4 * w)) & 15);
    if (seg != 15) {
        int eq = seg * 32 + lane;
        const bool v = eq < NPAIR;
        if (!v) eq = 0;
        int q = 0;
        while ((q + 1) * (q + 2) / 2 <= eq) q++;
        int p = eq - q * (q + 1) / 2;
        int rb = 0;
        for (int pp = 0; pp < p; pp++) rb += (MF - pp) * (MF - pp + 1) / 2;
        for (int qq = p; qq < q; qq++) rb += MF - qq;
        const int js = __shfl_sync(0xFFFFFFFFu, q, 0);

        ull xx[16];
#pragma unroll
        for (int cc = 0; cc < 8; cc++) {
            ulonglong2 xp = *reinterpret_cast<const ulonglong2*>(&xsr[p][2 * cc]);
            ulonglong2 xq = *reinterpret_cast<const ulonglong2*>(&xsr[q][2 * cc]);
            MUL2(xx[2 * cc],     xp.x, xq.x);
            MUL2(xx[2 * cc + 1], xp.y, xq.y);
        }

        {   // G
            ull g0 = 0, g1 = 0;
#pragma unroll
            for (int kp = 0; kp < 16; kp += 2) { ADD2(g0, xx[kp]); ADD2(g1, xx[kp + 1]); }
            ADD2(g0, g1);
            if (v) sF[pq_off(p) + q - p] = hadd2(g0);
        }

        for (int j = js; j < MF; j++) {
            ull a0 = 0, a1 = 0, a2 = 0, a3 = 0;
#pragma unroll
            for (int cc = 0; cc < 8; cc++) {
                ulonglong2 xj = *reinterpret_cast<const ulonglong2*>(&xsr[j][2 * cc]);
                if (cc & 1) { FMA2(a2, xx[2 * cc], xj.x); FMA2(a3, xx[2 * cc + 1], xj.y); }
                else        { FMA2(a0, xx[2 * cc], xj.x); FMA2(a1, xx[2 * cc + 1], xj.y); }
            }
            ADD2(a0, a1); ADD2(a2, a3); ADD2(a0, a2);
            if (v && j >= q) sF[352 + rb + j - q] = hadd2(a0);
        }
    }
    __syncthreads();

    // G-vector fp16 hi/lo [b][384]
    {
        int e = t;
        float val = (e < NPAIR) ? sF[e] : (e == NPAIR ? 32.0f : 0.0f);
        __half hi = __float2half_rn(val);
        float lo = val - __half2float(hi);
        size_t o = (size_t)b * 384 + e;
        g_TFh[o] = hi;
        g_TFl[o] = __float2half_rn(lo);
    }

    // T-vector fp16 hi/lo [b][3328]
    for (int e = t; e < NJ; e += 384) {
        float val;
        if (e < NTRI)            val = sF[352 + e];
        else if (e < NTRI + MF)  val = sF[3628 + (e - NTRI)];
        else if (e == NTRI + MF) val = 32.0f;
        else                     val = 0.0f;
        __half hi = __float2half_rn(val);
        float lo = val - __half2float(hi);
        size_t o = (size_t)b * NJ + e;
        g_Th[o] = hi;
        g_Tl[o] = __float2half_rn(lo);
    }
}

// ---------------------------------------------------------------------------
// k_u: U = W1s @ W2t. 48m x 128n tiles, grid 208, 384 thr.
// ---------------------------------------------------------------------------
__global__ __launch_bounds__(384) void k_u() {
    __shared__ float As[32][52];
    __shared__ float Bs[32][132];
    const int t = threadIdx.x;
    int m0 = (blockIdx.x & 7) * 48;
    int n0 = (blockIdx.x >> 3) * 128;
    const int tx = t & 31, ty = t >> 5;

    ull acc[4][2];
#pragma unroll
    for (int r = 0; r < 4; r++) { acc[r][0] = 0ULL; acc[r][1] = 0ULL; }

    for (int kc = 0; kc < 128; kc += 32) {
        __syncthreads();
        {
            int row = t >> 3, c4 = t & 7;
            float4 v = *reinterpret_cast<const float4*>(
                g_W1s + (size_t)(m0 + row) * 128 + kc + 4 * c4);
            As[4 * c4 + 0][row] = v.x;
            As[4 * c4 + 1][row] = v.y;
            As[4 * c4 + 2][row] = v.z;
            As[4 * c4 + 3][row] = v.w;
        }
#pragma unroll
        for (int l = 0; l < 3; l++) {
            int idx = t + 384 * l;
            if (idx < 1024) {
                int row = idx >> 5, c4 = idx & 31;
                *reinterpret_cast<float4*>(&Bs[row][4 * c4]) =
                    *reinterpret_cast<const float4*>(g_W2t + (size_t)(kc + row) * NJ + n0 + 4 * c4);
            }
        }
        __syncthreads();

#pragma unroll
        for (int kk = 0; kk < 32; kk++) {
            float4 a = *reinterpret_cast<const float4*>(&As[kk][4 * ty]);
            ulonglong2 wv = *reinterpret_cast<const ulonglong2*>(&Bs[kk][4 * tx]);
            ull d;
            DUP2(d, a.x); FMA2(acc[0][0], wv.x, d); FMA2(acc[0][1], wv.y, d);
            DUP2(d, a.y); FMA2(acc[1][0], wv.x, d); FMA2(acc[1][1], wv.y, d);
            DUP2(d, a.z); FMA2(acc[2][0], wv.x, d); FMA2(acc[2][1], wv.y, d);
            DUP2(d, a.w); FMA2(acc[3][0], wv.x, d); FMA2(acc[3][1], wv.y, d);
        }
    }
#pragma unroll
    for (int r = 0; r < 4; r++) {
        int m = m0 + 4 * ty + r;
        if (m < 352) {
            float* dst = g_U + (size_t)m * NJ + n0 + 4 * tx;
            *reinterpret_cast<float2*>(dst)     = *reinterpret_cast<float2*>(&acc[r][0]);
            *reinterpret_cast<float2*>(dst + 2) = *reinterpret_cast<float2*>(&acc[r][1]);
        }
    }
}

// ---------------------------------------------------------------------------
// k_fold: grid (52,4) — 64e x 32h tiles, warp-uniform e reads, smem
//   transpose, e-coalesced fp16 writes.
// ---------------------------------------------------------------------------
__global__ __launch_bounds__(256) void k_fold(const float* __restrict__ b2) {
    __shared__ float tile[64][33];
    const int t  = threadIdx.x;
    const int e0 = blockIdx.x * 64;
    const int h0 = blockIdx.y * 32;
    const int hl = t & 31;
    const int h  = h0 + hl;
    const int er = t >> 5;

#pragma unroll
    for (int i = 0; i < 8; i++) {
        int el = er + 8 * i;
        int e = e0 + el;
        float val = 0.f;
        if (e < NTRI) {
            int c = g_e2pqj[e];
            int p = c & 255, q = (c >> 8) & 255, j = (c >> 16) & 255;
            #define CU(PQ, J) g_U[(size_t)(PQ) * NJ + (J) * 128 + h]
            if (p < q) {
                if (q < j) val = CU(pq_off(p) + q - p, j) + CU(pq_off(p) + j - p, q) + CU(pq_off(q) + j - q, p);
                else       val = CU(pq_off(p) + q - p, q) + CU(pq_off(q), p);
            } else {
                if (q < j) val = CU(pq_off(p), j) + CU(pq_off(p) + j - p, p);
                else       val = CU(pq_off(p), p);
            }
            #undef CU
        } else if (e < NTRI + MF) {
            val = g_U[(size_t)NPAIR * NJ + (e - NTRI) * 128 + h];
        } else if (e == NTRI + MF) {
            val = b2[h];
        }
        tile[el][hl] = val;
    }
    __syncthreads();

#pragma unroll
    for (int i = 0; i < 8; i++) {
        int idx = t + 256 * i;
        int h2 = idx >> 6;
        int el = idx & 63;
        float val = tile[el][h2];
        __half hi = __float2half_rn(val);
        float lo = val - __half2float(hi);
        size_t o = (size_t)(h0 + h2) * NJ + e0 + el;
        g_Uh[o] = hi;
        g_Ul[o] = __float2half_rn(lo);
    }
}

// ---------------------------------------------------------------------------
// k_tc: grid 288 (single wave at 2 CTAs/SM), all HMMA, dyn smem 96K.
//   id<256: gemm1 tile (bt=id>>3, ks=id&7; chunks 7/7/7/7/6/6/6/6) -> g_P[ks]
//   id>=256: gemm0 tile (K=384, 6 chunks) -> out cols 0..127
// ---------------------------------------------------------------------------
#define STAGE_BYTES 49152
__global__ __launch_bounds__(256) void k_tc(float* __restrict__ out) {
    extern __shared__ __align__(16) char dyn[];
    const int t = threadIdx.x;
    const int id = blockIdx.x;
    const int wid = t >> 5, lane = t & 31;
    const int wm = wid >> 2, wn = wid & 3;
    const int mr0 = 32 * wm, nr0 = 32 * wn;

    const __half *Ah, *Al, *Bh, *Bl;
    int astr, bstr, nch, kbase, b0;
    float* dst;
    int dstr;
    if (id < 256) {
        int bt = id >> 3, ks = id & 7;
        b0 = bt * 64;
        Ah = g_Th; Al = g_Tl; Bh = g_Uh; Bl = g_Ul;
        astr = NJ; bstr = NJ;
        nch = (ks < 4) ? 7 : 6;
        kbase = 64 * ((ks < 4) ? 7 * ks : 28 + 6 * (ks - 4));
        dst = g_P + (size_t)ks * BATCH * 128;
        dstr = 128;
    } else {
        b0 = (id - 256) * 64;
        Ah = g_TFh; Al = g_TFl; Bh = g_W1h; Bl = g_W1l;
        astr = 384; bstr = 384;
        nch = 6; kbase = 0;
        dst = out;
        dstr = OUTW;
    }

    const uint32_t sBase = sptr(dyn);

    float d[2][4][4];
#pragma unroll
    for (int mf = 0; mf < 2; mf++)
#pragma unroll
        for (int nf = 0; nf < 4; nf++)
#pragma unroll
            for (int e = 0; e < 4; e++) d[mf][nf][e] = 0.f;

    const int aR = t >> 3, aC = t & 7;
    const uint32_t aSw0 = (uint32_t)(aR * 128 + ((aC ^ (aR & 7)) << 4));
    const int aR1 = (t + 256) >> 3;
    const uint32_t aSw1 = (uint32_t)(aR1 * 128 + ((aC ^ (aR1 & 7)) << 4));

    // ldmatrix lane-address components
    const int aRowOff = lane & 15;
    const uint32_t aColX = (uint32_t)((lane >> 4) << 4);
    // B x4: lanes 0-7 (nf,k0), 8-15 (nf,k1), 16-23 (nf+1,k0), 24-31 (nf+1,k1)
    const int bRow4 = (lane & 7) + ((lane >> 4) << 3);
    const uint32_t bCol4 = (uint32_t)(((lane >> 3) & 1) << 4);

    auto stage_issue = [&](int ch) {
        const int kc = kbase + ch * 64;
        const uint32_t sb = sBase + (uint32_t)(ch & 1) * STAGE_BYTES;
        {
            size_t go0 = (size_t)(b0 + aR) * astr + kc + aC * 8;
            size_t go1 = (size_t)(b0 + aR1) * astr + kc + aC * 8;
            cp16(sb + aSw0,        Ah + go0);
            cp16(sb + 8192 + aSw0, Al + go0);
            cp16(sb + aSw1,        Ah + go1);
            cp16(sb + 8192 + aSw1, Al + go1);
        }
#pragma unroll
        for (int i = 0; i < 4; i++) {
            int u = t + 256 * i;
            int r = u >> 3, c8 = u & 7;
            uint32_t sw = (uint32_t)(r * 128 + ((c8 ^ (r & 7)) << 4));
            size_t go = (size_t)r * bstr + kc + c8 * 8;
            cp16(sb + 16384 + sw, Bh + go);
            cp16(sb + 32768 + sw, Bl + go);
        }
        CP_COMMIT();
    };

    stage_issue(0);
    if (nch > 1) stage_issue(1);

    for (int ch = 0; ch < nch; ch++) {
        if (ch + 1 < nch) { CP_WAIT1(); } else { CP_WAIT0(); }
        __syncthreads();

        const uint32_t sb = sBase + (uint32_t)(ch & 1) * STAGE_BYTES;
        const uint32_t sA = sb, sB = sb + 16384;

#pragma unroll
        for (int k16 = 0; k16 < 4; k16++) {
            uint32_t ah[2][4], al[2][4], bhf[4][2], blf[4][2];
#pragma unroll
            for (int mf = 0; mf < 2; mf++) {
                int row = mr0 + 16 * mf + aRowOff;
                uint32_t colb = (uint32_t)(k16 * 32) + aColX;
                uint32_t addr = sA + (uint32_t)(row * 128) + (colb ^ ((uint32_t)(row & 7) << 4));
                LDSM4(ah[mf][0], ah[mf][1], ah[mf][2], ah[mf][3], addr);
                LDSM4(al[mf][0], al[mf][1], al[mf][2], al[mf][3], addr + 8192);
            }
#pragma unroll
            for (int p2 = 0; p2 < 2; p2++) {
                int row = nr0 + 16 * p2 + bRow4;
                uint32_t colb = (uint32_t)(k16 * 32) + bCol4;
                uint32_t addr = sB + (uint32_t)(row * 128) + (colb ^ ((uint32_t)(row & 7) << 4));
                LDSM4(bhf[2 * p2][0], bhf[2 * p2][1], bhf[2 * p2 + 1][0], bhf[2 * p2 + 1][1], addr);
                LDSM4(blf[2 * p2][0], blf[2 * p2][1], blf[2 * p2 + 1][0], blf[2 * p2 + 1][1], addr + 16384);
            }
#pragma unroll
            for (int mf = 0; mf < 2; mf++)
#pragma unroll
                for (int nf = 0; nf < 4; nf++) {
                    MMA16816(d[mf][nf], ah[mf], bhf[nf]);
                    MMA16816(d[mf][nf], ah[mf], blf[nf]);
                    MMA16816(d[mf][nf], al[mf], bhf[nf]);
                }
        }

        __syncthreads();
        if (ch + 2 < nch) stage_issue(ch + 2);
    }

    const int g = lane >> 2, tq = lane & 3;
#pragma unroll
    for (int mf = 0; mf < 2; mf++) {
        int rbase = b0 + mr0 + 16 * mf;
#pragma unroll
        for (int nf = 0; nf < 4; nf++) {
            int h = nr0 + 8 * nf + 2 * tq;
            *reinterpret_cast<float2*>(dst + (size_t)(rbase + g) * dstr + h) =
                make_float2(d[mf][nf][0], d[mf][nf][1]);
            *reinterpret_cast<float2*>(dst + (size_t)(rbase + g + 8) * dstr + h) =
                make_float2(d[mf][nf][2], d[mf][nf][3]);
        }
    }
}

// ---------------------------------------------------------------------------
// k_red: out[:,128:256] = sum of 8 partials
// ---------------------------------------------------------------------------
__global__ void k_red(float* __restrict__ out) {
    int gid = blockIdx.x * blockDim.x + threadIdx.x;
    int b = gid >> 7, h = gid & 127;
    const int N = BATCH * 128;
    float s0 = g_P[gid]         + g_P[gid + N];
    float s1 = g_P[gid + 2 * N] + g_P[gid + 3 * N];
    float s2 = g_P[gid + 4 * N] + g_P[gid + 5 * N];
    float s3 = g_P[gid + 6 * N] + g_P[gid + 7 * N];
    out[(size_t)b * OUTW + 128 + h] = (s0 + s1) + (s2 + s3);
}

// ---------------------------------------------------------------------------
// launch: two-stream graph.
//   stream2: kA_prep -> k_u -> k_fold  (weight chain)
//   capture stream: k_feat (concurrent) -> join -> k_tc -> k_red
// ---------------------------------------------------------------------------
extern "C" void kernel_launch(void* const* d_in, const int* in_sizes, int n_in,
                              void* d_out, int out_size) {
    const float* inputs = (const float*)d_in[0];
    const float* W1     = (const float*)d_in[1];
    const float* b1     = (const float*)d_in[2];
    const float* W2     = (const float*)d_in[3];
    const float* b2     = (const float*)d_in[4];
    float* out = (float*)d_out;

    cudaFuncSetAttribute(k_tc, cudaFuncAttributeMaxDynamicSharedMemorySize, 2 * STAGE_BYTES);

    cudaStream_t s2;
    cudaStreamCreateWithFlags(&s2, cudaStreamNonBlocking);
    cudaEvent_t evFork, evJoin;
    cudaEventCreateWithFlags(&evFork, cudaEventDisableTiming);
    cudaEventCreateWithFlags(&evJoin, cudaEventDisableTiming);

    cudaEventRecord(evFork, 0);
    cudaStreamWaitEvent(s2, evFork, 0);

    kA_prep<<<621, 256, 0, s2>>>(W1, b1, W2);
    k_u<<<208, 384, 0, s2>>>();
    k_fold<<<dim3(52, 4), 256, 0, s2>>>(b2);
    cudaEventRecord(evJoin, s2);

    k_feat<<<BATCH, 384>>>(inputs);

    cudaStreamWaitEvent(0, evJoin, 0);
    k_tc<<<288, 256, 2 * STAGE_BYTES>>>(out);
    k_red<<<(BATCH * 128) / 256, 256>>>(out);

    cudaEventDestroy(evFork);
    cudaEventDestroy(evJoin);
    cudaStreamDestroy(s2);
}